// round 7
// baseline (speedup 1.0000x reference)
#include <cuda_runtime.h>
#include <cuda_bf16.h>
#include <cstdint>

#define BB   512
#define CC   3
#define TT   500
#define DD   40
#define CD   120
#define NN   256
#define OUTN 12
#define BN   (BB*NN)        // 131072
#define B_J0 0.01f
#define BETA 1.8f

// ------------------------- device scratch (allocation-guard-safe) -----------
__device__ float         g_i1[(size_t)TT * BB * NN];   // 262 MB (i1, then i2in)
__device__ unsigned char g_lst[(size_t)TT * BB * 256]; // 65.5 MB s1 index lists
__device__ int           g_cnt[TT * BB];               // list lengths
__device__ float         g_W2inQ[4 * 256 * 64];        // [q][j][nl] quarters
__device__ float         g_W2recTp[NN * NN];           // [j][n]
__device__ float         g_acc[BB * OUTN];

// ------------------------- packed f32x2 helpers -----------------------------
__device__ __forceinline__ unsigned long long pack_dup(float a) {
    unsigned long long r;
    asm("mov.b64 %0, {%1,%1};" : "=l"(r) : "f"(a));
    return r;
}
__device__ __forceinline__ void unpack2(unsigned long long v, float& a, float& b) {
    asm("mov.b64 {%0,%1}, %2;" : "=f"(a), "=f"(b) : "l"(v));
}
__device__ __forceinline__ void fma2(unsigned long long& acc,
                                     unsigned long long a, unsigned long long b) {
    asm("fma.rn.f32x2 %0, %1, %2, %0;" : "+l"(acc) : "l"(a), "l"(b));
}

// ------------------------- cluster / mbarrier helpers -----------------------
__device__ __forceinline__ unsigned smem_u32(const void* p) {
    return (unsigned)__cvta_generic_to_shared(p);
}
__device__ __forceinline__ void mbar_init(unsigned addr, unsigned count) {
    asm volatile("mbarrier.init.shared.b64 [%0], %1;" :: "r"(addr), "r"(count) : "memory");
}
__device__ __forceinline__ void st_cluster_u32(unsigned laddr, unsigned peer, unsigned v) {
    asm volatile("{\n\t.reg .b32 ra;\n\t"
                 "mapa.shared::cluster.u32 ra, %0, %1;\n\t"
                 "st.shared::cluster.u32 [ra], %2;\n\t}"
                 :: "r"(laddr), "r"(peer), "r"(v) : "memory");
}
__device__ __forceinline__ void mbar_arrive_peer(unsigned laddr, unsigned peer) {
    asm volatile("{\n\t.reg .b32 ra;\n\t"
                 "mapa.shared::cluster.u32 ra, %0, %1;\n\t"
                 "mbarrier.arrive.release.cluster.shared::cluster.b64 _, [ra];\n\t}"
                 :: "r"(laddr), "r"(peer) : "memory");
}
__device__ __forceinline__ void mbar_wait(unsigned addr, unsigned parity) {
    asm volatile(
        "{\n\t.reg .pred P;\n\t"
        "WAITL_%=:\n\t"
        "mbarrier.try_wait.parity.acquire.cluster.shared::cta.b64 P, [%0], %1, 0x989680;\n\t"
        "@P bra.uni WAITD_%=;\n\t"
        "bra.uni WAITL_%=;\n\t"
        "WAITD_%=:\n\t}"
        :: "r"(addr), "r"(parity) : "memory");
}
__device__ __forceinline__ void cluster_sync_() {
    asm volatile("barrier.cluster.arrive.aligned;" ::: "memory");
    asm volatile("barrier.cluster.wait.aligned;"   ::: "memory");
}

// ------------------------- K0: weight layout prep ---------------------------
__global__ void k0_prep(const float* __restrict__ W2_in,
                        const float* __restrict__ W2_rec)
{
    int j = blockIdx.x;        // presyn 0..255
    int n = threadIdx.x;       // postsyn 0..255
    g_W2recTp[j * NN + n] = W2_rec[n * NN + j];
    g_W2inQ[(((n >> 6) * 256) + j) * 64 + (n & 63)] = W2_in[n * NN + j];
}

// ------------------------- K1: spikify + i1 GEMM ----------------------------
// grid 4000 x 256. smem: w1t[120][256] + xs2(ull)[120][64] + shared raw/stage.
// W1 transpose goes through raw[n][31] (stride 31 coprime 32 -> conflict-free
// on both sides), replacing the old 30-way-conflicted direct STS.
#define K1_SMEM (122880 + 61440 + 31744)
__global__ void __launch_bounds__(256, 1)
k1_gemm1(const float* __restrict__ x, const float* __restrict__ thrp,
         const float* __restrict__ W1, const float* __restrict__ b1)
{
    extern __shared__ float sm[];
    float*              w1t   = sm;                                   // [k][n]
    unsigned long long* xs2   = (unsigned long long*)(sm + 120 * 256);// [k][r] dup
    float*              shb   = (float*)(xs2 + 120 * 64);             // raw / stage

    const int tid = threadIdx.x;
    const int p0  = blockIdx.x * 64;
    const int t   = p0 >> 9;
    const int b0  = p0 & 511;
    const float thr = *thrp;

    // ---- W1 -> w1t via 4 conflict-free chunks (30 k each) ----
    {
        const float2* W1f2 = (const float2*)W1;
        float* raw = shb;                         // [n][31]
        #pragma unroll 1
        for (int c = 0; c < 4; c++) {
            for (int i = tid; i < 3840; i += 256) {
                int n = i / 15, f = i % 15;
                float2 v = W1f2[n * 60 + c * 15 + f];
                raw[n * 31 + 2 * f]     = v.x;
                raw[n * 31 + 2 * f + 1] = v.y;
            }
            __syncthreads();
            #pragma unroll 1
            for (int it = 0; it < 30; it++)
                w1t[(c * 30 + it) * 256 + tid] = raw[tid * 31 + it];
            __syncthreads();
        }
    }
    // ---- spikify -> stage[r][121] ----
    {
        float* stage = shb;
        for (int i = tid; i < 64 * CD; i += 256) {
            int r  = i / CD;
            int cd = i % CD;
            int c  = cd / DD, d = cd % DD;
            int b  = b0 + r;
            float xv = x[(((size_t)b * CC + c) * TT + t) * DD + d];
            float s  = (xv > thr) ? 1.0f : ((xv < -thr) ? -1.0f : 0.0f);
            stage[r * 121 + cd] = s;
        }
        __syncthreads();
        for (int i = tid; i < CD * 64; i += 256) {
            int cd = i >> 6;
            int r  = i & 63;
            xs2[cd * 64 + r] = pack_dup(stage[r * 121 + cd]);
        }
        __syncthreads();
    }

    // ---- main: 8 rows x 8 n per thread ----
    const int ng = tid & 31;
    const int rg = tid >> 5;
    unsigned long long acc[32];
    #pragma unroll
    for (int i = 0; i < 32; i++) acc[i] = 0ull;

    #pragma unroll 2
    for (int k = 0; k < CD; k++) {
        const ulonglong2* wp = (const ulonglong2*)(w1t + k * NN + (ng << 3));
        ulonglong2 wA = wp[0];
        ulonglong2 wB = wp[1];
        const ulonglong2* xp = (const ulonglong2*)(xs2 + k * 64 + (rg << 3));
        ulonglong2 x01 = xp[0], x23 = xp[1], x45 = xp[2], x67 = xp[3];
        unsigned long long xd[8] = {x01.x, x01.y, x23.x, x23.y,
                                    x45.x, x45.y, x67.x, x67.y};
        #pragma unroll
        for (int rr = 0; rr < 8; rr++) {
            fma2(acc[rr * 4 + 0], xd[rr], wA.x);
            fma2(acc[rr * 4 + 1], xd[rr], wA.y);
            fma2(acc[rr * 4 + 2], xd[rr], wB.x);
            fma2(acc[rr * 4 + 3], xd[rr], wB.y);
        }
    }

    float4 bq0 = *(const float4*)(b1 + (ng << 3));
    float4 bq1 = *(const float4*)(b1 + (ng << 3) + 4);
    #pragma unroll
    for (int rr = 0; rr < 8; rr++) {
        float o[8];
        #pragma unroll
        for (int np = 0; np < 4; np++)
            unpack2(acc[rr * 4 + np], o[2 * np], o[2 * np + 1]);
        o[0] += bq0.x; o[1] += bq0.y; o[2] += bq0.z; o[3] += bq0.w;
        o[4] += bq1.x; o[5] += bq1.y; o[6] += bq1.z; o[7] += bq1.w;
        size_t base = (size_t)t * BN + (size_t)(b0 + rg * 8 + rr) * NN + (ng << 3);
        *(float4*)&g_i1[base]     = make_float4(o[0], o[1], o[2], o[3]);
        *(float4*)&g_i1[base + 4] = make_float4(o[4], o[5], o[6], o[7]);
    }
}

// ------------------------- K2: layer-1 ALIF scan -> compacted s1 lists ------
__global__ void __launch_bounds__(256)
k2_scan1(const float* __restrict__ tau_adp1, const float* __restrict__ tau_m1)
{
    __shared__ unsigned swords[2][8];

    const int b    = blockIdx.x;
    const int tid  = threadIdx.x;
    const int n    = tid;
    const int lane = tid & 31;
    const int wid  = tid >> 5;
    const unsigned ltm = (1u << lane) - 1u;

    const float alpha = __expf(-1.0f / tau_m1[n]);
    const float rho   = __expf(-1.0f / tau_adp1[n]);
    const float ca = 1.0f - alpha, cr = 1.0f - rho;

    float m = 0.f, a = B_J0, s = 0.f;
    const float* ip = g_i1 + (size_t)b * NN + n;

    for (int t4 = 0; t4 < TT; t4 += 4) {
        float iv[4];
        #pragma unroll
        for (int k = 0; k < 4; k++) iv[k] = ip[(size_t)(t4 + k) * BN];
        #pragma unroll
        for (int k = 0; k < 4; k++) {
            const int t = t4 + k;
            a = rho * a + cr * s;
            float Bth = B_J0 + BETA * a;
            m = alpha * m + ca * iv[k] - Bth * s;
            s = (m - Bth > 0.f) ? 1.f : 0.f;
            unsigned bal = __ballot_sync(0xffffffffu, s > 0.5f);
            if (lane == 0) swords[t & 1][wid] = bal;
            __syncthreads();
            unsigned wv[8];
            #pragma unroll
            for (int w = 0; w < 8; w++) wv[w] = swords[t & 1][w];
            int off = 0, myoff = 0;
            #pragma unroll
            for (int w = 0; w < 8; w++) {
                if (w == wid) myoff = off;
                off += __popc(wv[w]);
            }
            unsigned wd = wv[wid];
            if ((wd >> lane) & 1u)
                g_lst[(size_t)(t * BB + b) * 256 + myoff + __popc(wd & ltm)] =
                    (unsigned char)(wid * 32 + lane);
            if (tid == 0) g_cnt[t * BB + b] = off;
        }
    }
}

// ------------------------- K2.5: i2in = b2 + s1 @ W2_in^T (unchanged R5) ----
#define K25_SMEM (64*1024 + 8*2*64*4)
__global__ void __launch_bounds__(256, 2)
k25_gemm2in(const float* __restrict__ b2_in, const float* __restrict__ b2_rec)
{
    extern __shared__ float sm[];
    float2*   w2  = (float2*)sm;                  // [j*32+lane] pairs
    unsigned* lsb = (unsigned*)(sm + 16384);      // [8 warps][2][64]

    const int idx  = blockIdx.x;
    const int q    = idx & 3;
    const int bh   = (idx >> 2) & 1;
    const int t    = idx >> 3;
    const int tid  = threadIdx.x;
    const int lane = tid & 31;
    const int wid  = tid >> 5;

    {
        const float4* src = (const float4*)(g_W2inQ + q * 256 * 64);
        float4* dst = (float4*)sm;
        for (int i = tid; i < 4096; i += 256) dst[i] = src[i];
    }
    const int n0 = q * 64 + lane * 2;
    const float2 bias2 = make_float2(b2_in[n0] + b2_rec[n0],
                                     b2_in[n0 + 1] + b2_rec[n0 + 1]);
    __syncthreads();

    const int bbase = bh * 256 + wid * 32;
    const int cb    = t * BB + bbase;
    const int mycnt = g_cnt[cb + lane];
    unsigned* mybuf = lsb + wid * 128;

    {
        int c0  = __shfl_sync(0xffffffffu, mycnt, 0);
        int nch = (c0 + 15) >> 4;
        if (lane < nch) {
            uint4 v = ((const uint4*)(g_lst + (size_t)cb * 256))[lane];
            unsigned* d = mybuf + lane * 4;
            d[0] = v.x; d[1] = v.y; d[2] = v.z; d[3] = v.w;
        }
        __syncwarp();
    }

    for (int i = 0; i < 32; i++) {
        uint4 vn = make_uint4(0, 0, 0, 0);
        int nchn = 0;
        if (i + 1 < 32) {
            int cn = __shfl_sync(0xffffffffu, mycnt, i + 1);
            nchn = (cn + 15) >> 4;
            if (lane < nchn)
                vn = ((const uint4*)(g_lst + (size_t)(cb + i + 1) * 256))[lane];
        }
        const int cnt = __shfl_sync(0xffffffffu, mycnt, i);
        const unsigned* lb = mybuf + (i & 1) * 64;

        float2 acc = bias2;
        int k = 0;
        for (; k + 4 <= cnt; k += 4) {
            unsigned w = lb[k >> 2];
            int j0 = w & 255, j1 = (w >> 8) & 255, j2 = (w >> 16) & 255, j3 = w >> 24;
            float2 v0 = w2[j0 * 32 + lane];
            float2 v1 = w2[j1 * 32 + lane];
            float2 v2 = w2[j2 * 32 + lane];
            float2 v3 = w2[j3 * 32 + lane];
            acc.x += v0.x; acc.y += v0.y;
            acc.x += v1.x; acc.y += v1.y;
            acc.x += v2.x; acc.y += v2.y;
            acc.x += v3.x; acc.y += v3.y;
        }
        if (k < cnt) {
            unsigned w = lb[k >> 2];
            for (; k < cnt; k++) {
                int j = (w >> (8 * (k & 3))) & 255;
                float2 v = w2[j * 32 + lane];
                acc.x += v.x; acc.y += v.y;
            }
        }

        ((float2*)(g_i1 + (size_t)t * BN + (size_t)(bbase + i) * NN + q * 64))[lane] = acc;

        if (i + 1 < 32 && lane < nchn) {
            unsigned* d = mybuf + ((i + 1) & 1) * 64 + lane * 4;
            d[0] = vn.x; d[1] = vn.y; d[2] = vn.z; d[3] = vn.w;
        }
        __syncwarp();
    }
}

// ------------------------- K3: recurrent core, 2-CTA clusters ---------------
// 128 clusters x 2 CTAs x 512 threads. CTA rank r: W2rec^T columns for its
// 128 neurons (full j range) in smem. 4 batches/cluster (slot = tid>>7).
// Per step: conflict-free smem gather over compacted s2 list; ballots
// exchanged via st.shared::cluster + mbarrier (release/acquire, parity).
// Rank 0 runs layer-3 with full W3 (exact R5 ordering).
#define K3_SMEM (16 + 256 + 4096 + OUTN*257*4 + 256*128*4)
__global__ void __cluster_dims__(2, 1, 1) __launch_bounds__(512, 1)
k3_recurrent(const float* __restrict__ W3, const float* __restrict__ b3,
             const float* __restrict__ tau_adp2, const float* __restrict__ tau_m2,
             const float* __restrict__ tau_m3)
{
    extern __shared__ char smc[];
    unsigned long long* mbar  = (unsigned long long*)smc;            // [2]
    unsigned*           words = (unsigned*)(smc + 16);               // [2][4][8]
    int*                lst   = (int*)(smc + 16 + 256);              // [4][256]
    float*              W3s   = (float*)(smc + 16 + 256 + 4096);     // [12][257]
    float*              w2h   = (float*)(smc + 16 + 256 + 4096 + OUTN*257*4); // [j][nl]

    const unsigned rank = (unsigned)(blockIdx.x & 1);
    const int tid  = threadIdx.x;
    const int lane = tid & 31;
    const int wid  = tid >> 5;      // 0..15
    const int s    = wid >> 2;      // batch slot 0..3
    const int ws   = wid & 3;       // warp within slot
    const int nl   = tid & 127;
    const int n    = (int)rank * 128 + nl;
    const int b    = (blockIdx.x >> 1) * 4 + s;
    const unsigned ltm = (1u << lane) - 1u;

    // init
    if (tid == 0) {
        mbar_init(smem_u32(&mbar[0]), 16);
        mbar_init(smem_u32(&mbar[1]), 16);
    }
    for (int i = tid; i < 64; i += 512) words[i] = 0u;
    for (int i = tid; i < OUTN * NN; i += 512)
        W3s[(i >> 8) * 257 + (i & 255)] = W3[i];
    for (int i = tid; i < 256 * 128; i += 512)
        w2h[i] = g_W2recTp[(i >> 7) * NN + (int)rank * 128 + (i & 127)];

    const float al = __expf(-1.0f / tau_m2[n]);
    const float rh = __expf(-1.0f / tau_adp2[n]);
    float m2 = 0.f, a2 = B_J0, s2 = 0.f;

    // layer-3 (rank 0, lanes nl<12 of ws==0 warps)
    float al3 = 1.f, m3 = 0.f, accr = 0.f, b3v = 0.f;
    const bool do3 = (rank == 0) && (nl < OUTN) && (ws == 0);
    if (do3) { al3 = __expf(-1.0f / tau_m3[nl]); b3v = b3[nl]; }

    const unsigned mb0 = smem_u32(&mbar[0]);
    const unsigned mb1 = smem_u32(&mbar[1]);
    const unsigned peer = rank ^ 1u;

    __syncthreads();
    cluster_sync_();     // mbar init + zeroed words visible cluster-wide

    const float* __restrict__ i2p = g_i1 + (size_t)b * NN + n;
    float iv = i2p[0];
    int par0 = 0, par1 = 0;

    for (int t = 0; t < TT; t++) {
        const int ph = t & 1;

        const int tn = (t + 1 < TT) ? (t + 1) : t;
        float nv = i2p[(size_t)tn * BN];

        if (t > 0) {
            if (ph) { mbar_wait(mb1, par1); par1 ^= 1; }
            else    { mbar_wait(mb0, par0); par0 ^= 1; }
        }
        __syncthreads();   // local words from prev step + lst reuse

        // compaction of slot's 8 words (ascending j)
        unsigned wv[8];
        #pragma unroll
        for (int w = 0; w < 8; w++) wv[w] = words[(ph * 4 + s) * 8 + w];
        int off[8], cnt = 0;
        #pragma unroll
        for (int w = 0; w < 8; w++) { off[w] = cnt; cnt += __popc(wv[w]); }
        {
            unsigned wd = wv[ws];
            if ((wd >> lane) & 1u)
                lst[s * 256 + off[ws] + __popc(wd & ltm)] = ws * 32 + lane;
            wd = wv[ws + 4];
            if ((wd >> lane) & 1u)
                lst[s * 256 + off[ws + 4] + __popc(wd & ltm)] = (ws + 4) * 32 + lane;
        }
        __syncthreads();   // lists ready

        // deferred layer-3 for step t-1 (same list = s2(t-1))
        if (do3 && t > 0) {
            float i3 = b3v;
            const float* wr = &W3s[nl * 257];
            const int* ml = lst + s * 256;
            for (int k = 0; k < cnt; k++) i3 += wr[ml[k]];
            m3 = al3 * m3 + (1.0f - al3) * i3;
            accr += m3;
        }

        // recurrent gather from smem (conflict-free, 8-way batched)
        float i2 = iv;
        {
            const int* ml = lst + s * 256;
            int k = 0;
            for (; k + 8 <= cnt; k += 8) {
                int j0 = ml[k],     j1 = ml[k + 1], j2 = ml[k + 2], j3 = ml[k + 3];
                int j4 = ml[k + 4], j5 = ml[k + 5], j6 = ml[k + 6], j7 = ml[k + 7];
                float v0 = w2h[j0 * 128 + nl];
                float v1 = w2h[j1 * 128 + nl];
                float v2 = w2h[j2 * 128 + nl];
                float v3 = w2h[j3 * 128 + nl];
                float v4 = w2h[j4 * 128 + nl];
                float v5 = w2h[j5 * 128 + nl];
                float v6 = w2h[j6 * 128 + nl];
                float v7 = w2h[j7 * 128 + nl];
                i2 += v0; i2 += v1; i2 += v2; i2 += v3;
                i2 += v4; i2 += v5; i2 += v6; i2 += v7;
            }
            for (; k < cnt; k++) i2 += w2h[ml[k] * 128 + nl];
        }

        // ALIF update
        a2 = rh * a2 + (1.0f - rh) * s2;
        float Bth = B_J0 + BETA * a2;
        m2 = al * m2 + (1.0f - al) * i2 - Bth * s2;
        s2 = (m2 - Bth > 0.f) ? 1.f : 0.f;

        unsigned bal = __ballot_sync(0xffffffffu, s2 > 0.5f);
        const int nxt = ph ^ 1;
        if (lane == 0) {
            const unsigned widx = (unsigned)((nxt * 4 + s) * 8 + (int)rank * 4 + ws);
            words[widx] = bal;                                     // local
            st_cluster_u32(smem_u32(&words[widx]), peer, bal);     // peer
        }
        // every warp's lane0 arrives on PEER's bar[nxt] (count 16)
        if (lane == 0) mbar_arrive_peer(nxt ? mb1 : mb0, peer);

        iv = nv;
    }

    // final exchange (written at t=TT-1 into phase TT&1 = 0)
    mbar_wait(mb0, par0);
    __syncthreads();
    if (do3) {
        unsigned wv[8];
        #pragma unroll
        for (int w = 0; w < 8; w++) wv[w] = words[(0 * 4 + s) * 8 + w];
        float i3 = b3v;
        const float* wr = &W3s[nl * 257];
        #pragma unroll
        for (int w = 0; w < 8; w++) {
            unsigned mm = wv[w];
            int base = w * 32;
            while (mm) {
                int j = __ffs((int)mm) - 1;
                mm &= mm - 1;
                i3 += wr[base + j];
            }
        }
        m3 = al3 * m3 + (1.0f - al3) * i3;
        accr += m3;
        g_acc[b * OUTN + nl] = accr;
    }
    cluster_sync_();
}

// ------------------------- K4: log-softmax ----------------------------------
__global__ void __launch_bounds__(256)
k4_softmax(float* __restrict__ out)
{
    int b = blockIdx.x * 256 + threadIdx.x;
    if (b >= BB) return;
    float v[OUTN];
    float mx = -1e30f;
    #pragma unroll
    for (int o = 0; o < OUTN; o++) {
        v[o] = g_acc[b * OUTN + o] * (1.0f / (float)TT);
        mx = fmaxf(mx, v[o]);
    }
    float sum = 0.f;
    #pragma unroll
    for (int o = 0; o < OUTN; o++) sum += __expf(v[o] - mx);
    float lse = mx + __logf(sum);
    #pragma unroll
    for (int o = 0; o < OUTN; o++) out[b * OUTN + o] = v[o] - lse;
}

// ------------------------- launch -------------------------------------------
extern "C" void kernel_launch(void* const* d_in, const int* in_sizes, int n_in,
                              void* d_out, int out_size)
{
    const float* x        = (const float*)d_in[0];
    const float* thr      = (const float*)d_in[1];
    const float* W1       = (const float*)d_in[2];
    const float* b1       = (const float*)d_in[3];
    const float* W2_in    = (const float*)d_in[4];
    const float* b2_in    = (const float*)d_in[5];
    const float* W2_rec   = (const float*)d_in[6];
    const float* b2_rec   = (const float*)d_in[7];
    const float* W3       = (const float*)d_in[8];
    const float* b3       = (const float*)d_in[9];
    const float* tau_adp1 = (const float*)d_in[10];
    const float* tau_m1   = (const float*)d_in[11];
    const float* tau_adp2 = (const float*)d_in[12];
    const float* tau_m2   = (const float*)d_in[13];
    const float* tau_m3   = (const float*)d_in[14];
    float* out = (float*)d_out;

    cudaFuncSetAttribute(k1_gemm1,     cudaFuncAttributeMaxDynamicSharedMemorySize, K1_SMEM);
    cudaFuncSetAttribute(k25_gemm2in,  cudaFuncAttributeMaxDynamicSharedMemorySize, K25_SMEM);
    cudaFuncSetAttribute(k3_recurrent, cudaFuncAttributeMaxDynamicSharedMemorySize, K3_SMEM);

    k0_prep<<<NN, NN>>>(W2_in, W2_rec);
    k1_gemm1<<<(TT * BB) / 64, 256, K1_SMEM>>>(x, thr, W1, b1);
    k2_scan1<<<BB, 256>>>(tau_adp1, tau_m1);
    k25_gemm2in<<<8 * TT, 256, K25_SMEM>>>(b2_in, b2_rec);
    k3_recurrent<<<256, 512, K3_SMEM>>>(W3, b3, tau_adp2, tau_m2, tau_m3);
    k4_softmax<<<(BB + 255) / 256, 256>>>(out);
}

// round 9
// speedup vs baseline: 1.0910x; 1.0910x over previous
#include <cuda_runtime.h>
#include <cuda_bf16.h>
#include <cstdint>

#define BB   512
#define CC   3
#define TT   500
#define DD   40
#define CD   120
#define NN   256
#define OUTN 12
#define BN   (BB*NN)        // 131072
#define B_J0 0.01f
#define BETA 1.8f

// ------------------------- device scratch (allocation-guard-safe) -----------
__device__ float         g_i1[(size_t)TT * BB * NN];   // 262 MB (i1, then i2in)
__device__ unsigned char g_lst[(size_t)TT * BB * 256]; // 65.5 MB s1 index lists
__device__ int           g_cnt[TT * BB];               // list lengths
__device__ float         g_W2inQ[4 * 256 * 64];        // [q][j][nl] quarters
__device__ float         g_W2recTp[NN * NN];           // [j][n]
__device__ float         g_acc[BB * OUTN];

// ------------------------- packed f32x2 helpers -----------------------------
__device__ __forceinline__ unsigned long long pack_dup(float a) {
    unsigned long long r;
    asm("mov.b64 %0, {%1,%1};" : "=l"(r) : "f"(a));
    return r;
}
__device__ __forceinline__ void unpack2(unsigned long long v, float& a, float& b) {
    asm("mov.b64 {%0,%1}, %2;" : "=f"(a), "=f"(b) : "l"(v));
}
__device__ __forceinline__ void fma2(unsigned long long& acc,
                                     unsigned long long a, unsigned long long b) {
    asm("fma.rn.f32x2 %0, %1, %2, %0;" : "+l"(acc) : "l"(a), "l"(b));
}

// ------------------------- cluster / mbarrier helpers -----------------------
__device__ __forceinline__ unsigned smem_u32(const void* p) {
    return (unsigned)__cvta_generic_to_shared(p);
}
__device__ __forceinline__ void mbar_init(unsigned addr, unsigned count) {
    asm volatile("mbarrier.init.shared.b64 [%0], %1;" :: "r"(addr), "r"(count) : "memory");
}
__device__ __forceinline__ void st_cluster_u32(unsigned laddr, unsigned peer, unsigned v) {
    asm volatile("{\n\t.reg .b32 ra;\n\t"
                 "mapa.shared::cluster.u32 ra, %0, %1;\n\t"
                 "st.shared::cluster.u32 [ra], %2;\n\t}"
                 :: "r"(laddr), "r"(peer), "r"(v) : "memory");
}
__device__ __forceinline__ void mbar_arrive_peer(unsigned laddr, unsigned peer) {
    asm volatile("{\n\t.reg .b32 ra;\n\t"
                 "mapa.shared::cluster.u32 ra, %0, %1;\n\t"
                 "mbarrier.arrive.release.cluster.shared::cluster.b64 _, [ra];\n\t}"
                 :: "r"(laddr), "r"(peer) : "memory");
}
__device__ __forceinline__ void mbar_wait(unsigned addr, unsigned parity) {
    asm volatile(
        "{\n\t.reg .pred P;\n\t"
        "WAITL_%=:\n\t"
        "mbarrier.try_wait.parity.acquire.cluster.shared::cta.b64 P, [%0], %1, 0x989680;\n\t"
        "@P bra.uni WAITD_%=;\n\t"
        "bra.uni WAITL_%=;\n\t"
        "WAITD_%=:\n\t}"
        :: "r"(addr), "r"(parity) : "memory");
}
__device__ __forceinline__ void cluster_sync_() {
    asm volatile("barrier.cluster.arrive.aligned;" ::: "memory");
    asm volatile("barrier.cluster.wait.aligned;"   ::: "memory");
}

// ------------------------- K0: weight layout prep ---------------------------
__global__ void k0_prep(const float* __restrict__ W2_in,
                        const float* __restrict__ W2_rec)
{
    int j = blockIdx.x;        // presyn 0..255
    int n = threadIdx.x;       // postsyn 0..255
    g_W2recTp[j * NN + n] = W2_rec[n * NN + j];
    g_W2inQ[(((n >> 6) * 256) + j) * 64 + (n & 63)] = W2_in[n * NN + j];
}

// ------------------------- K1: spikify + i1 GEMM ----------------------------
#define K1_SMEM (122880 + 61440 + 31744)
__global__ void __launch_bounds__(256, 1)
k1_gemm1(const float* __restrict__ x, const float* __restrict__ thrp,
         const float* __restrict__ W1, const float* __restrict__ b1)
{
    extern __shared__ float sm[];
    float*              w1t   = sm;                                   // [k][n]
    unsigned long long* xs2   = (unsigned long long*)(sm + 120 * 256);// [k][r] dup
    float*              shb   = (float*)(xs2 + 120 * 64);             // raw / stage

    const int tid = threadIdx.x;
    const int p0  = blockIdx.x * 64;
    const int t   = p0 >> 9;
    const int b0  = p0 & 511;
    const float thr = *thrp;

    // ---- W1 -> w1t via 4 conflict-free chunks (stride-31 staging) ----
    {
        const float2* W1f2 = (const float2*)W1;
        float* raw = shb;                         // [n][31]
        #pragma unroll 1
        for (int c = 0; c < 4; c++) {
            for (int i = tid; i < 3840; i += 256) {
                int n = i / 15, f = i % 15;
                float2 v = W1f2[n * 60 + c * 15 + f];
                raw[n * 31 + 2 * f]     = v.x;
                raw[n * 31 + 2 * f + 1] = v.y;
            }
            __syncthreads();
            #pragma unroll 1
            for (int it = 0; it < 30; it++)
                w1t[(c * 30 + it) * 256 + tid] = raw[tid * 31 + it];
            __syncthreads();
        }
    }
    // ---- spikify -> stage[r][121] -> xs2 ----
    {
        float* stage = shb;
        for (int i = tid; i < 64 * CD; i += 256) {
            int r  = i / CD;
            int cd = i % CD;
            int c  = cd / DD, d = cd % DD;
            int b  = b0 + r;
            float xv = x[(((size_t)b * CC + c) * TT + t) * DD + d];
            float s  = (xv > thr) ? 1.0f : ((xv < -thr) ? -1.0f : 0.0f);
            stage[r * 121 + cd] = s;
        }
        __syncthreads();
        for (int i = tid; i < CD * 64; i += 256) {
            int cd = i >> 6;
            int r  = i & 63;
            xs2[cd * 64 + r] = pack_dup(stage[r * 121 + cd]);
        }
        __syncthreads();
    }

    // ---- main: 8 rows x 8 n per thread ----
    const int ng = tid & 31;
    const int rg = tid >> 5;
    unsigned long long acc[32];
    #pragma unroll
    for (int i = 0; i < 32; i++) acc[i] = 0ull;

    #pragma unroll 2
    for (int k = 0; k < CD; k++) {
        const ulonglong2* wp = (const ulonglong2*)(w1t + k * NN + (ng << 3));
        ulonglong2 wA = wp[0];
        ulonglong2 wB = wp[1];
        const ulonglong2* xp = (const ulonglong2*)(xs2 + k * 64 + (rg << 3));
        ulonglong2 x01 = xp[0], x23 = xp[1], x45 = xp[2], x67 = xp[3];
        unsigned long long xd[8] = {x01.x, x01.y, x23.x, x23.y,
                                    x45.x, x45.y, x67.x, x67.y};
        #pragma unroll
        for (int rr = 0; rr < 8; rr++) {
            fma2(acc[rr * 4 + 0], xd[rr], wA.x);
            fma2(acc[rr * 4 + 1], xd[rr], wA.y);
            fma2(acc[rr * 4 + 2], xd[rr], wB.x);
            fma2(acc[rr * 4 + 3], xd[rr], wB.y);
        }
    }

    float4 bq0 = *(const float4*)(b1 + (ng << 3));
    float4 bq1 = *(const float4*)(b1 + (ng << 3) + 4);
    #pragma unroll
    for (int rr = 0; rr < 8; rr++) {
        float o[8];
        #pragma unroll
        for (int np = 0; np < 4; np++)
            unpack2(acc[rr * 4 + np], o[2 * np], o[2 * np + 1]);
        o[0] += bq0.x; o[1] += bq0.y; o[2] += bq0.z; o[3] += bq0.w;
        o[4] += bq1.x; o[5] += bq1.y; o[6] += bq1.z; o[7] += bq1.w;
        size_t base = (size_t)t * BN + (size_t)(b0 + rg * 8 + rr) * NN + (ng << 3);
        *(float4*)&g_i1[base]     = make_float4(o[0], o[1], o[2], o[3]);
        *(float4*)&g_i1[base + 4] = make_float4(o[4], o[5], o[6], o[7]);
    }
}

// ------------------------- K2: layer-1 ALIF scan -> compacted s1 lists ------
__global__ void __launch_bounds__(256)
k2_scan1(const float* __restrict__ tau_adp1, const float* __restrict__ tau_m1)
{
    __shared__ unsigned swords[2][8];

    const int b    = blockIdx.x;
    const int tid  = threadIdx.x;
    const int n    = tid;
    const int lane = tid & 31;
    const int wid  = tid >> 5;
    const unsigned ltm = (1u << lane) - 1u;

    const float alpha = __expf(-1.0f / tau_m1[n]);
    const float rho   = __expf(-1.0f / tau_adp1[n]);
    const float ca = 1.0f - alpha, cr = 1.0f - rho;

    float m = 0.f, a = B_J0, s = 0.f;
    const float* ip = g_i1 + (size_t)b * NN + n;

    for (int t4 = 0; t4 < TT; t4 += 4) {
        float iv[4];
        #pragma unroll
        for (int k = 0; k < 4; k++) iv[k] = ip[(size_t)(t4 + k) * BN];
        #pragma unroll
        for (int k = 0; k < 4; k++) {
            const int t = t4 + k;
            a = rho * a + cr * s;
            float Bth = B_J0 + BETA * a;
            m = alpha * m + ca * iv[k] - Bth * s;
            s = (m - Bth > 0.f) ? 1.f : 0.f;
            unsigned bal = __ballot_sync(0xffffffffu, s > 0.5f);
            if (lane == 0) swords[t & 1][wid] = bal;
            __syncthreads();
            unsigned wv[8];
            #pragma unroll
            for (int w = 0; w < 8; w++) wv[w] = swords[t & 1][w];
            int off = 0, myoff = 0;
            #pragma unroll
            for (int w = 0; w < 8; w++) {
                if (w == wid) myoff = off;
                off += __popc(wv[w]);
            }
            unsigned wd = wv[wid];
            if ((wd >> lane) & 1u)
                g_lst[(size_t)(t * BB + b) * 256 + myoff + __popc(wd & ltm)] =
                    (unsigned char)(wid * 32 + lane);
            if (tid == 0) g_cnt[t * BB + b] = off;
        }
    }
}

// ------------------------- K2.5: i2in = b2 + s1 @ W2_in^T (unchanged) -------
#define K25_SMEM (64*1024 + 8*2*64*4)
__global__ void __launch_bounds__(256, 2)
k25_gemm2in(const float* __restrict__ b2_in, const float* __restrict__ b2_rec)
{
    extern __shared__ float sm[];
    float2*   w2  = (float2*)sm;                  // [j*32+lane] pairs
    unsigned* lsb = (unsigned*)(sm + 16384);      // [8 warps][2][64]

    const int idx  = blockIdx.x;
    const int q    = idx & 3;
    const int bh   = (idx >> 2) & 1;
    const int t    = idx >> 3;
    const int tid  = threadIdx.x;
    const int lane = tid & 31;
    const int wid  = tid >> 5;

    {
        const float4* src = (const float4*)(g_W2inQ + q * 256 * 64);
        float4* dst = (float4*)sm;
        for (int i = tid; i < 4096; i += 256) dst[i] = src[i];
    }
    const int n0 = q * 64 + lane * 2;
    const float2 bias2 = make_float2(b2_in[n0] + b2_rec[n0],
                                     b2_in[n0 + 1] + b2_rec[n0 + 1]);
    __syncthreads();

    const int bbase = bh * 256 + wid * 32;
    const int cb    = t * BB + bbase;
    const int mycnt = g_cnt[cb + lane];
    unsigned* mybuf = lsb + wid * 128;

    {
        int c0  = __shfl_sync(0xffffffffu, mycnt, 0);
        int nch = (c0 + 15) >> 4;
        if (lane < nch) {
            uint4 v = ((const uint4*)(g_lst + (size_t)cb * 256))[lane];
            unsigned* d = mybuf + lane * 4;
            d[0] = v.x; d[1] = v.y; d[2] = v.z; d[3] = v.w;
        }
        __syncwarp();
    }

    for (int i = 0; i < 32; i++) {
        uint4 vn = make_uint4(0, 0, 0, 0);
        int nchn = 0;
        if (i + 1 < 32) {
            int cn = __shfl_sync(0xffffffffu, mycnt, i + 1);
            nchn = (cn + 15) >> 4;
            if (lane < nchn)
                vn = ((const uint4*)(g_lst + (size_t)(cb + i + 1) * 256))[lane];
        }
        const int cnt = __shfl_sync(0xffffffffu, mycnt, i);
        const unsigned* lb = mybuf + (i & 1) * 64;

        float2 acc = bias2;
        int k = 0;
        for (; k + 4 <= cnt; k += 4) {
            unsigned w = lb[k >> 2];
            int j0 = w & 255, j1 = (w >> 8) & 255, j2 = (w >> 16) & 255, j3 = w >> 24;
            float2 v0 = w2[j0 * 32 + lane];
            float2 v1 = w2[j1 * 32 + lane];
            float2 v2 = w2[j2 * 32 + lane];
            float2 v3 = w2[j3 * 32 + lane];
            acc.x += v0.x; acc.y += v0.y;
            acc.x += v1.x; acc.y += v1.y;
            acc.x += v2.x; acc.y += v2.y;
            acc.x += v3.x; acc.y += v3.y;
        }
        if (k < cnt) {
            unsigned w = lb[k >> 2];
            for (; k < cnt; k++) {
                int j = (w >> (8 * (k & 3))) & 255;
                float2 v = w2[j * 32 + lane];
                acc.x += v.x; acc.y += v.y;
            }
        }

        ((float2*)(g_i1 + (size_t)t * BN + (size_t)(bbase + i) * NN + q * 64))[lane] = acc;

        if (i + 1 < 32 && lane < nchn) {
            unsigned* d = mybuf + ((i + 1) & 1) * 64 + lane * 4;
            d[0] = vn.x; d[1] = vn.y; d[2] = vn.z; d[3] = vn.w;
        }
        __syncwarp();
    }
}

// ------------------------- K3: recurrent core, 2-CTA clusters, ONE WAVE -----
// 74 clusters x 2 CTAs = 148 CTAs (exactly one wave). 896 threads = 28 warps,
// 7 batch slots per cluster (74*7 = 518 >= 512; overflow slots clamp loads,
// skip stores, still hit every barrier). CTA rank r holds W2rec^T columns for
// its 128 neurons (full j range, 128 KB) in smem. Ballot exchange via
// st.shared::cluster + mbarrier (count 28).
#define K3S    7
#define K3TPB  (K3S*128)
#define K3_SMEM (16 + 2*K3S*8*4 + K3S*256*4 + OUTN*257*4 + 256*128*4)
__global__ void __cluster_dims__(2, 1, 1) __launch_bounds__(K3TPB, 1)
k3_recurrent(const float* __restrict__ W3, const float* __restrict__ b3,
             const float* __restrict__ tau_adp2, const float* __restrict__ tau_m2,
             const float* __restrict__ tau_m3)
{
    extern __shared__ char smc[];
    unsigned long long* mbar  = (unsigned long long*)smc;                 // [2]
    unsigned*           words = (unsigned*)(smc + 16);                    // [2][7][8]
    int*                lst   = (int*)(smc + 16 + 2*K3S*8*4);             // [7][256]
    float*              W3s   = (float*)(smc + 16 + 2*K3S*8*4 + K3S*256*4);
    float*              w2h   = (float*)(smc + 16 + 2*K3S*8*4 + K3S*256*4 + OUTN*257*4);

    const unsigned rank = (unsigned)(blockIdx.x & 1);
    const int tid  = threadIdx.x;
    const int lane = tid & 31;
    const int wid  = tid >> 5;      // 0..27
    const int s    = wid >> 2;      // batch slot 0..6
    const int ws   = wid & 3;       // warp within slot
    const int nl   = tid & 127;
    const int n    = (int)rank * 128 + nl;
    const int b    = (blockIdx.x >> 1) * K3S + s;
    const bool bvalid = (b < BB);
    const int bsafe = bvalid ? b : 0;
    const unsigned ltm = (1u << lane) - 1u;

    if (tid == 0) {
        mbar_init(smem_u32(&mbar[0]), 28);
        mbar_init(smem_u32(&mbar[1]), 28);
    }
    for (int i = tid; i < 2 * K3S * 8; i += K3TPB) words[i] = 0u;
    for (int i = tid; i < OUTN * NN; i += K3TPB)
        W3s[(i >> 8) * 257 + (i & 255)] = W3[i];
    for (int i = tid; i < 256 * 128; i += K3TPB)
        w2h[i] = g_W2recTp[(i >> 7) * NN + (int)rank * 128 + (i & 127)];

    const float al = __expf(-1.0f / tau_m2[n]);
    const float rh = __expf(-1.0f / tau_adp2[n]);
    float m2 = 0.f, a2 = B_J0, s2 = 0.f;

    float al3 = 1.f, m3 = 0.f, accr = 0.f, b3v = 0.f;
    const bool do3 = (rank == 0) && (nl < OUTN) && (ws == 0);
    if (do3) { al3 = __expf(-1.0f / tau_m3[nl]); b3v = b3[nl]; }

    const unsigned mb0 = smem_u32(&mbar[0]);
    const unsigned mb1 = smem_u32(&mbar[1]);
    const unsigned peer = rank ^ 1u;

    __syncthreads();
    cluster_sync_();

    const float* __restrict__ i2p = g_i1 + (size_t)bsafe * NN + n;
    float iv = i2p[0];
    int par0 = 0, par1 = 0;

    for (int t = 0; t < TT; t++) {
        const int ph = t & 1;

        const int tn = (t + 1 < TT) ? (t + 1) : t;
        float nv = i2p[(size_t)tn * BN];

        if (t > 0) {
            if (ph) { mbar_wait(mb1, par1); par1 ^= 1; }
            else    { mbar_wait(mb0, par0); par0 ^= 1; }
        }
        __syncthreads();

        // compaction of slot's 8 words (ascending j)
        unsigned wv[8];
        #pragma unroll
        for (int w = 0; w < 8; w++) wv[w] = words[(ph * K3S + s) * 8 + w];
        int off[8], cnt = 0;
        #pragma unroll
        for (int w = 0; w < 8; w++) { off[w] = cnt; cnt += __popc(wv[w]); }
        {
            unsigned wd = wv[ws];
            if ((wd >> lane) & 1u)
                lst[s * 256 + off[ws] + __popc(wd & ltm)] = ws * 32 + lane;
            wd = wv[ws + 4];
            if ((wd >> lane) & 1u)
                lst[s * 256 + off[ws + 4] + __popc(wd & ltm)] = (ws + 4) * 32 + lane;
        }
        __syncthreads();

        // deferred layer-3 for step t-1 (list = s2(t-1))
        if (do3 && t > 0) {
            float i3 = b3v;
            const float* wr = &W3s[nl * 257];
            const int* ml = lst + s * 256;
            for (int k = 0; k < cnt; k++) i3 += wr[ml[k]];
            m3 = al3 * m3 + (1.0f - al3) * i3;
            accr += m3;
        }

        // recurrent gather from smem (conflict-free, 8-way batched)
        float i2 = iv;
        {
            const int* ml = lst + s * 256;
            int k = 0;
            for (; k + 8 <= cnt; k += 8) {
                int j0 = ml[k],     j1 = ml[k + 1], j2 = ml[k + 2], j3 = ml[k + 3];
                int j4 = ml[k + 4], j5 = ml[k + 5], j6 = ml[k + 6], j7 = ml[k + 7];
                float v0 = w2h[j0 * 128 + nl];
                float v1 = w2h[j1 * 128 + nl];
                float v2 = w2h[j2 * 128 + nl];
                float v3 = w2h[j3 * 128 + nl];
                float v4 = w2h[j4 * 128 + nl];
                float v5 = w2h[j5 * 128 + nl];
                float v6 = w2h[j6 * 128 + nl];
                float v7 = w2h[j7 * 128 + nl];
                i2 += v0; i2 += v1; i2 += v2; i2 += v3;
                i2 += v4; i2 += v5; i2 += v6; i2 += v7;
            }
            for (; k < cnt; k++) i2 += w2h[ml[k] * 128 + nl];
        }

        // ALIF update
        a2 = rh * a2 + (1.0f - rh) * s2;
        float Bth = B_J0 + BETA * a2;
        m2 = al * m2 + (1.0f - al) * i2 - Bth * s2;
        s2 = (m2 - Bth > 0.f) ? 1.f : 0.f;

        unsigned bal = __ballot_sync(0xffffffffu, s2 > 0.5f);
        const int nxt = ph ^ 1;
        if (lane == 0) {
            const unsigned widx = (unsigned)((nxt * K3S + s) * 8 + (int)rank * 4 + ws);
            words[widx] = bal;                                     // local
            st_cluster_u32(smem_u32(&words[widx]), peer, bal);     // peer
        }
        if (lane == 0) mbar_arrive_peer(nxt ? mb1 : mb0, peer);

        iv = nv;
    }

    // final deferred layer-3 (step TT-1's ballots live in phase 0)
    mbar_wait(mb0, par0);
    __syncthreads();
    if (do3 && bvalid) {
        unsigned wv[8];
        #pragma unroll
        for (int w = 0; w < 8; w++) wv[w] = words[(0 * K3S + s) * 8 + w];
        float i3 = b3v;
        const float* wr = &W3s[nl * 257];
        #pragma unroll
        for (int w = 0; w < 8; w++) {
            unsigned mm = wv[w];
            int base = w * 32;
            while (mm) {
                int j = __ffs((int)mm) - 1;
                mm &= mm - 1;
                i3 += wr[base + j];
            }
        }
        m3 = al3 * m3 + (1.0f - al3) * i3;
        accr += m3;
        g_acc[b * OUTN + nl] = accr;
    }
    cluster_sync_();
}

// ------------------------- K4: log-softmax ----------------------------------
__global__ void __launch_bounds__(256)
k4_softmax(float* __restrict__ out)
{
    int b = blockIdx.x * 256 + threadIdx.x;
    if (b >= BB) return;
    float v[OUTN];
    float mx = -1e30f;
    #pragma unroll
    for (int o = 0; o < OUTN; o++) {
        v[o] = g_acc[b * OUTN + o] * (1.0f / (float)TT);
        mx = fmaxf(mx, v[o]);
    }
    float sum = 0.f;
    #pragma unroll
    for (int o = 0; o < OUTN; o++) sum += __expf(v[o] - mx);
    float lse = mx + __logf(sum);
    #pragma unroll
    for (int o = 0; o < OUTN; o++) out[b * OUTN + o] = v[o] - lse;
}

// ------------------------- launch -------------------------------------------
extern "C" void kernel_launch(void* const* d_in, const int* in_sizes, int n_in,
                              void* d_out, int out_size)
{
    const float* x        = (const float*)d_in[0];
    const float* thr      = (const float*)d_in[1];
    const float* W1       = (const float*)d_in[2];
    const float* b1       = (const float*)d_in[3];
    const float* W2_in    = (const float*)d_in[4];
    const float* b2_in    = (const float*)d_in[5];
    const float* W2_rec   = (const float*)d_in[6];
    const float* b2_rec   = (const float*)d_in[7];
    const float* W3       = (const float*)d_in[8];
    const float* b3       = (const float*)d_in[9];
    const float* tau_adp1 = (const float*)d_in[10];
    const float* tau_m1   = (const float*)d_in[11];
    const float* tau_adp2 = (const float*)d_in[12];
    const float* tau_m2   = (const float*)d_in[13];
    const float* tau_m3   = (const float*)d_in[14];
    float* out = (float*)d_out;

    cudaFuncSetAttribute(k1_gemm1,     cudaFuncAttributeMaxDynamicSharedMemorySize, K1_SMEM);
    cudaFuncSetAttribute(k25_gemm2in,  cudaFuncAttributeMaxDynamicSharedMemorySize, K25_SMEM);
    cudaFuncSetAttribute(k3_recurrent, cudaFuncAttributeMaxDynamicSharedMemorySize, K3_SMEM);

    k0_prep<<<NN, NN>>>(W2_in, W2_rec);
    k1_gemm1<<<(TT * BB) / 64, 256, K1_SMEM>>>(x, thr, W1, b1);
    k2_scan1<<<BB, 256>>>(tau_adp1, tau_m1);
    k25_gemm2in<<<8 * TT, 256, K25_SMEM>>>(b2_in, b2_rec);
    k3_recurrent<<<148, K3TPB, K3_SMEM>>>(W3, b3, tau_adp2, tau_m2, tau_m3);
    k4_softmax<<<(BB + 255) / 256, 256>>>(out);
}

// round 10
// speedup vs baseline: 1.3535x; 1.2406x over previous
#include <cuda_runtime.h>
#include <cuda_bf16.h>
#include <cstdint>

#define BB   512
#define CC   3
#define TT   500
#define DD   40
#define CD   120
#define NN   256
#define OUTN 12
#define BN   (BB*NN)        // 131072
#define B_J0 0.01f
#define BETA 1.8f

// ------------------------- device scratch (allocation-guard-safe) -----------
__device__ float         g_i1[(size_t)TT * BB * NN];   // 262 MB (i1, then i2in)
__device__ unsigned char g_lst[(size_t)TT * BB * 256]; // 65.5 MB s1 index lists
__device__ int           g_cnt[TT * BB];               // list lengths
__device__ float         g_W2inQ[4 * 256 * 64];        // [q][j][nl] quarters
__device__ float         g_W2recTp[NN * NN];           // [j][n]
__device__ float         g_acc[BB * OUTN];

// ------------------------- packed f32x2 helpers -----------------------------
__device__ __forceinline__ unsigned long long pack_dup(float a) {
    unsigned long long r;
    asm("mov.b64 %0, {%1,%1};" : "=l"(r) : "f"(a));
    return r;
}
__device__ __forceinline__ void unpack2(unsigned long long v, float& a, float& b) {
    asm("mov.b64 {%0,%1}, %2;" : "=f"(a), "=f"(b) : "l"(v));
}
__device__ __forceinline__ void fma2(unsigned long long& acc,
                                     unsigned long long a, unsigned long long b) {
    asm("fma.rn.f32x2 %0, %1, %2, %0;" : "+l"(acc) : "l"(a), "l"(b));
}

// ------------------------- K0: weight layout prep ---------------------------
__global__ void k0_prep(const float* __restrict__ W2_in,
                        const float* __restrict__ W2_rec)
{
    int j = blockIdx.x;        // presyn 0..255
    int n = threadIdx.x;       // postsyn 0..255
    g_W2recTp[j * NN + n] = W2_rec[n * NN + j];
    g_W2inQ[(((n >> 6) * 256) + j) * 64 + (n & 63)] = W2_in[n * NN + j];
}

// ------------------------- K1: spikify + i1 GEMM ----------------------------
// grid 4000 x 256. Conflict-free stride-31 staging for the W1 transpose.
#define K1_SMEM (122880 + 61440 + 31744)
__global__ void __launch_bounds__(256, 1)
k1_gemm1(const float* __restrict__ x, const float* __restrict__ thrp,
         const float* __restrict__ W1, const float* __restrict__ b1)
{
    extern __shared__ float sm[];
    float*              w1t   = sm;                                   // [k][n]
    unsigned long long* xs2   = (unsigned long long*)(sm + 120 * 256);// [k][r] dup
    float*              shb   = (float*)(xs2 + 120 * 64);             // raw / stage

    const int tid = threadIdx.x;
    const int p0  = blockIdx.x * 64;
    const int t   = p0 >> 9;
    const int b0  = p0 & 511;
    const float thr = *thrp;

    // ---- W1 -> w1t via 4 conflict-free chunks (stride-31 staging) ----
    {
        const float2* W1f2 = (const float2*)W1;
        float* raw = shb;                         // [n][31]
        #pragma unroll 1
        for (int c = 0; c < 4; c++) {
            for (int i = tid; i < 3840; i += 256) {
                int n = i / 15, f = i % 15;
                float2 v = W1f2[n * 60 + c * 15 + f];
                raw[n * 31 + 2 * f]     = v.x;
                raw[n * 31 + 2 * f + 1] = v.y;
            }
            __syncthreads();
            #pragma unroll 1
            for (int it = 0; it < 30; it++)
                w1t[(c * 30 + it) * 256 + tid] = raw[tid * 31 + it];
            __syncthreads();
        }
    }
    // ---- spikify -> stage[r][121] -> xs2 ----
    {
        float* stage = shb;
        for (int i = tid; i < 64 * CD; i += 256) {
            int r  = i / CD;
            int cd = i % CD;
            int c  = cd / DD, d = cd % DD;
            int b  = b0 + r;
            float xv = x[(((size_t)b * CC + c) * TT + t) * DD + d];
            float s  = (xv > thr) ? 1.0f : ((xv < -thr) ? -1.0f : 0.0f);
            stage[r * 121 + cd] = s;
        }
        __syncthreads();
        for (int i = tid; i < CD * 64; i += 256) {
            int cd = i >> 6;
            int r  = i & 63;
            xs2[cd * 64 + r] = pack_dup(stage[r * 121 + cd]);
        }
        __syncthreads();
    }

    // ---- main: 8 rows x 8 n per thread ----
    const int ng = tid & 31;
    const int rg = tid >> 5;
    unsigned long long acc[32];
    #pragma unroll
    for (int i = 0; i < 32; i++) acc[i] = 0ull;

    #pragma unroll 2
    for (int k = 0; k < CD; k++) {
        const ulonglong2* wp = (const ulonglong2*)(w1t + k * NN + (ng << 3));
        ulonglong2 wA = wp[0];
        ulonglong2 wB = wp[1];
        const ulonglong2* xp = (const ulonglong2*)(xs2 + k * 64 + (rg << 3));
        ulonglong2 x01 = xp[0], x23 = xp[1], x45 = xp[2], x67 = xp[3];
        unsigned long long xd[8] = {x01.x, x01.y, x23.x, x23.y,
                                    x45.x, x45.y, x67.x, x67.y};
        #pragma unroll
        for (int rr = 0; rr < 8; rr++) {
            fma2(acc[rr * 4 + 0], xd[rr], wA.x);
            fma2(acc[rr * 4 + 1], xd[rr], wA.y);
            fma2(acc[rr * 4 + 2], xd[rr], wB.x);
            fma2(acc[rr * 4 + 3], xd[rr], wB.y);
        }
    }

    float4 bq0 = *(const float4*)(b1 + (ng << 3));
    float4 bq1 = *(const float4*)(b1 + (ng << 3) + 4);
    #pragma unroll
    for (int rr = 0; rr < 8; rr++) {
        float o[8];
        #pragma unroll
        for (int np = 0; np < 4; np++)
            unpack2(acc[rr * 4 + np], o[2 * np], o[2 * np + 1]);
        o[0] += bq0.x; o[1] += bq0.y; o[2] += bq0.z; o[3] += bq0.w;
        o[4] += bq1.x; o[5] += bq1.y; o[6] += bq1.z; o[7] += bq1.w;
        size_t base = (size_t)t * BN + (size_t)(b0 + rg * 8 + rr) * NN + (ng << 3);
        *(float4*)&g_i1[base]     = make_float4(o[0], o[1], o[2], o[3]);
        *(float4*)&g_i1[base + 4] = make_float4(o[4], o[5], o[6], o[7]);
    }
}

// ------------------------- K2: layer-1 ALIF scan -> compacted s1 lists ------
__global__ void __launch_bounds__(256)
k2_scan1(const float* __restrict__ tau_adp1, const float* __restrict__ tau_m1)
{
    __shared__ unsigned swords[2][8];

    const int b    = blockIdx.x;
    const int tid  = threadIdx.x;
    const int n    = tid;
    const int lane = tid & 31;
    const int wid  = tid >> 5;
    const unsigned ltm = (1u << lane) - 1u;

    const float alpha = __expf(-1.0f / tau_m1[n]);
    const float rho   = __expf(-1.0f / tau_adp1[n]);
    const float ca = 1.0f - alpha, cr = 1.0f - rho;

    float m = 0.f, a = B_J0, s = 0.f;
    const float* ip = g_i1 + (size_t)b * NN + n;

    for (int t4 = 0; t4 < TT; t4 += 4) {
        float iv[4];
        #pragma unroll
        for (int k = 0; k < 4; k++) iv[k] = ip[(size_t)(t4 + k) * BN];
        #pragma unroll
        for (int k = 0; k < 4; k++) {
            const int t = t4 + k;
            a = rho * a + cr * s;
            float Bth = B_J0 + BETA * a;
            m = alpha * m + ca * iv[k] - Bth * s;
            s = (m - Bth > 0.f) ? 1.f : 0.f;
            unsigned bal = __ballot_sync(0xffffffffu, s > 0.5f);
            if (lane == 0) swords[t & 1][wid] = bal;
            __syncthreads();
            unsigned wv[8];
            #pragma unroll
            for (int w = 0; w < 8; w++) wv[w] = swords[t & 1][w];
            int off = 0, myoff = 0;
            #pragma unroll
            for (int w = 0; w < 8; w++) {
                if (w == wid) myoff = off;
                off += __popc(wv[w]);
            }
            unsigned wd = wv[wid];
            if ((wd >> lane) & 1u)
                g_lst[(size_t)(t * BB + b) * 256 + myoff + __popc(wd & ltm)] =
                    (unsigned char)(wid * 32 + lane);
            if (tid == 0) g_cnt[t * BB + b] = off;
        }
    }
}

// ------------------------- K2.5: i2in = b2 + s1 @ W2_in^T (proven R5) -------
#define K25_SMEM (64*1024 + 8*2*64*4)
__global__ void __launch_bounds__(256, 2)
k25_gemm2in(const float* __restrict__ b2_in, const float* __restrict__ b2_rec)
{
    extern __shared__ float sm[];
    float2*   w2  = (float2*)sm;                  // [j*32+lane] pairs
    unsigned* lsb = (unsigned*)(sm + 16384);      // [8 warps][2][64]

    const int idx  = blockIdx.x;
    const int q    = idx & 3;
    const int bh   = (idx >> 2) & 1;
    const int t    = idx >> 3;
    const int tid  = threadIdx.x;
    const int lane = tid & 31;
    const int wid  = tid >> 5;

    {
        const float4* src = (const float4*)(g_W2inQ + q * 256 * 64);
        float4* dst = (float4*)sm;
        for (int i = tid; i < 4096; i += 256) dst[i] = src[i];
    }
    const int n0 = q * 64 + lane * 2;
    const float2 bias2 = make_float2(b2_in[n0] + b2_rec[n0],
                                     b2_in[n0 + 1] + b2_rec[n0 + 1]);
    __syncthreads();

    const int bbase = bh * 256 + wid * 32;
    const int cb    = t * BB + bbase;
    const int mycnt = g_cnt[cb + lane];
    unsigned* mybuf = lsb + wid * 128;

    {
        int c0  = __shfl_sync(0xffffffffu, mycnt, 0);
        int nch = (c0 + 15) >> 4;
        if (lane < nch) {
            uint4 v = ((const uint4*)(g_lst + (size_t)cb * 256))[lane];
            unsigned* d = mybuf + lane * 4;
            d[0] = v.x; d[1] = v.y; d[2] = v.z; d[3] = v.w;
        }
        __syncwarp();
    }

    for (int i = 0; i < 32; i++) {
        uint4 vn = make_uint4(0, 0, 0, 0);
        int nchn = 0;
        if (i + 1 < 32) {
            int cn = __shfl_sync(0xffffffffu, mycnt, i + 1);
            nchn = (cn + 15) >> 4;
            if (lane < nchn)
                vn = ((const uint4*)(g_lst + (size_t)(cb + i + 1) * 256))[lane];
        }
        const int cnt = __shfl_sync(0xffffffffu, mycnt, i);
        const unsigned* lb = mybuf + (i & 1) * 64;

        float2 acc = bias2;
        int k = 0;
        for (; k + 4 <= cnt; k += 4) {
            unsigned w = lb[k >> 2];
            int j0 = w & 255, j1 = (w >> 8) & 255, j2 = (w >> 16) & 255, j3 = w >> 24;
            float2 v0 = w2[j0 * 32 + lane];
            float2 v1 = w2[j1 * 32 + lane];
            float2 v2 = w2[j2 * 32 + lane];
            float2 v3 = w2[j3 * 32 + lane];
            acc.x += v0.x; acc.y += v0.y;
            acc.x += v1.x; acc.y += v1.y;
            acc.x += v2.x; acc.y += v2.y;
            acc.x += v3.x; acc.y += v3.y;
        }
        if (k < cnt) {
            unsigned w = lb[k >> 2];
            for (; k < cnt; k++) {
                int j = (w >> (8 * (k & 3))) & 255;
                float2 v = w2[j * 32 + lane];
                acc.x += v.x; acc.y += v.y;
            }
        }

        ((float2*)(g_i1 + (size_t)t * BN + (size_t)(bbase + i) * NN + q * 64))[lane] = acc;

        if (i + 1 < 32 && lane < nchn) {
            unsigned* d = mybuf + ((i + 1) & 1) * 64 + lane * 4;
            d[0] = vn.x; d[1] = vn.y; d[2] = vn.z; d[3] = vn.w;
        }
        __syncwarp();
    }
}

// ------------------------- K3: sequential layer-2(rec) + layer-3 ------------
// Proven R5 design: 512 CTAs x 256 threads (1 neuron/thread), no clusters.
// i2in streamed with register prefetch; s2 gather list-compacted, 16-way
// batched LDG.32, in-order adds.
__global__ void __launch_bounds__(256)
k3_recurrent(const float* __restrict__ W3, const float* __restrict__ b3,
             const float* __restrict__ tau_adp2, const float* __restrict__ tau_m2,
             const float* __restrict__ tau_m3)
{
    __shared__ float    W3s[OUTN * 257];
    __shared__ unsigned words[8];
    __shared__ int      lst2[256];

    const int b    = blockIdx.x;
    const int tid  = threadIdx.x;
    const int n    = tid;
    const int lane = tid & 31;
    const int wid  = tid >> 5;
    const unsigned ltm = (1u << lane) - 1u;

    for (int i = tid; i < OUTN * NN; i += 256)
        W3s[(i >> 8) * 257 + (i & 255)] = W3[i];
    if (tid < 8) words[tid] = 0u;

    const float al = __expf(-1.0f / tau_m2[n]);
    const float rh = __expf(-1.0f / tau_adp2[n]);
    float m2 = 0.f, a2 = B_J0, s2 = 0.f;

    float al3 = 1.f, m3 = 0.f, accr = 0.f, b3v = 0.f;
    if (tid < OUTN) { al3 = __expf(-1.0f / tau_m3[tid]); b3v = b3[tid]; }

    const float* __restrict__ w2rf = g_W2recTp;
    const float* __restrict__ i2p  = g_i1 + (size_t)b * NN + n;

    __syncthreads();

    float iv = i2p[0];

    for (int t = 0; t < TT; t++) {
        __syncthreads();   // prev ballots visible; lst2 free

        const int tn = (t + 1 < TT) ? (t + 1) : t;
        float nv = i2p[(size_t)tn * BN];

        // deferred layer-3 for step t-1 (warp-0 lanes 0..11)
        if (tid < OUTN && t > 0) {
            float i3 = b3v;
            const float* wr = &W3s[tid * 257];
            #pragma unroll
            for (int w = 0; w < 8; w++) {
                unsigned mm = words[w];
                int base = w * 32;
                while (mm) {
                    int j = __ffs((int)mm) - 1;
                    mm &= mm - 1;
                    i3 += wr[base + j];
                }
            }
            m3 = al3 * m3 + (1.0f - al3) * i3;
            accr += m3;
        }

        // compaction (ascending j)
        unsigned wv[8];
        #pragma unroll
        for (int w = 0; w < 8; w++) wv[w] = words[w];
        int off = 0, myoff = 0;
        #pragma unroll
        for (int w = 0; w < 8; w++) {
            if (w == wid) myoff = off;
            off += __popc(wv[w]);
        }
        const int cnt2 = off;
        unsigned wd = wv[wid];
        if ((wd >> lane) & 1u)
            lst2[myoff + __popc(wd & ltm)] = wid * 32 + lane;
        __syncthreads();   // lists ready

        // gather: 16-way batched independent LDG.32, in-order adds
        float i2 = iv;
        {
            int k = 0;
            for (; k + 16 <= cnt2; k += 16) {
                float v[16];
                #pragma unroll
                for (int u = 0; u < 16; u++) v[u] = w2rf[lst2[k + u] * NN + n];
                #pragma unroll
                for (int u = 0; u < 16; u++) i2 += v[u];
            }
            for (; k + 4 <= cnt2; k += 4) {
                float v0 = w2rf[lst2[k] * NN + n];
                float v1 = w2rf[lst2[k + 1] * NN + n];
                float v2 = w2rf[lst2[k + 2] * NN + n];
                float v3 = w2rf[lst2[k + 3] * NN + n];
                i2 += v0; i2 += v1; i2 += v2; i2 += v3;
            }
            for (; k < cnt2; k++) i2 += w2rf[lst2[k] * NN + n];
        }

        // ALIF update
        a2 = rh * a2 + (1.0f - rh) * s2;
        float Bth = B_J0 + BETA * a2;
        m2 = al * m2 + (1.0f - al) * i2 - Bth * s2;
        s2 = (m2 - Bth > 0.f) ? 1.f : 0.f;

        unsigned bal = __ballot_sync(0xffffffffu, s2 > 0.5f);
        if (lane == 0) words[wid] = bal;
        iv = nv;
    }

    // final deferred layer-3 (step TT-1)
    __syncthreads();
    if (tid < OUTN) {
        float i3 = b3v;
        const float* wr = &W3s[tid * 257];
        #pragma unroll
        for (int w = 0; w < 8; w++) {
            unsigned mm = words[w];
            int base = w * 32;
            while (mm) {
                int j = __ffs((int)mm) - 1;
                mm &= mm - 1;
                i3 += wr[base + j];
            }
        }
        m3 = al3 * m3 + (1.0f - al3) * i3;
        accr += m3;
        g_acc[b * OUTN + tid] = accr;
    }
}

// ------------------------- K4: log-softmax ----------------------------------
__global__ void __launch_bounds__(256)
k4_softmax(float* __restrict__ out)
{
    int b = blockIdx.x * 256 + threadIdx.x;
    if (b >= BB) return;
    float v[OUTN];
    float mx = -1e30f;
    #pragma unroll
    for (int o = 0; o < OUTN; o++) {
        v[o] = g_acc[b * OUTN + o] * (1.0f / (float)TT);
        mx = fmaxf(mx, v[o]);
    }
    float sum = 0.f;
    #pragma unroll
    for (int o = 0; o < OUTN; o++) sum += __expf(v[o] - mx);
    float lse = mx + __logf(sum);
    #pragma unroll
    for (int o = 0; o < OUTN; o++) out[b * OUTN + o] = v[o] - lse;
}

// ------------------------- launch -------------------------------------------
extern "C" void kernel_launch(void* const* d_in, const int* in_sizes, int n_in,
                              void* d_out, int out_size)
{
    const float* x        = (const float*)d_in[0];
    const float* thr      = (const float*)d_in[1];
    const float* W1       = (const float*)d_in[2];
    const float* b1       = (const float*)d_in[3];
    const float* W2_in    = (const float*)d_in[4];
    const float* b2_in    = (const float*)d_in[5];
    const float* W2_rec   = (const float*)d_in[6];
    const float* b2_rec   = (const float*)d_in[7];
    const float* W3       = (const float*)d_in[8];
    const float* b3       = (const float*)d_in[9];
    const float* tau_adp1 = (const float*)d_in[10];
    const float* tau_m1   = (const float*)d_in[11];
    const float* tau_adp2 = (const float*)d_in[12];
    const float* tau_m2   = (const float*)d_in[13];
    const float* tau_m3   = (const float*)d_in[14];
    float* out = (float*)d_out;

    cudaFuncSetAttribute(k1_gemm1,    cudaFuncAttributeMaxDynamicSharedMemorySize, K1_SMEM);
    cudaFuncSetAttribute(k25_gemm2in, cudaFuncAttributeMaxDynamicSharedMemorySize, K25_SMEM);

    k0_prep<<<NN, NN>>>(W2_in, W2_rec);
    k1_gemm1<<<(TT * BB) / 64, 256, K1_SMEM>>>(x, thr, W1, b1);
    k2_scan1<<<BB, 256>>>(tau_adp1, tau_m1);
    k25_gemm2in<<<8 * TT, 256, K25_SMEM>>>(b2_in, b2_rec);
    k3_recurrent<<<BB, 256>>>(W3, b3, tau_adp2, tau_m2, tau_m3);
    k4_softmax<<<(BB + 255) / 256, 256>>>(out);
}

// round 11
// speedup vs baseline: 1.6913x; 1.2496x over previous
#include <cuda_runtime.h>
#include <cuda_bf16.h>
#include <cstdint>

#define BB   512
#define CC   3
#define TT   500
#define DD   40
#define CD   120
#define NN   256
#define OUTN 12
#define BN   (BB*NN)        // 131072
#define B_J0 0.01f
#define BETA 1.8f

// ------------------------- device scratch (allocation-guard-safe) -----------
__device__ float         g_i1[(size_t)TT * BB * NN];   // 262 MB (i1, then i2in)
__device__ unsigned char g_lst[(size_t)TT * BB * 256]; // 65.5 MB s1 index lists
__device__ int           g_cnt[TT * BB];               // list lengths
__device__ float         g_W2inQ[4 * 256 * 64];        // [q][j][nl] quarters
__device__ float         g_W2recTp[NN * NN];           // [j][n]
__device__ float         g_acc[BB * OUTN];

// ------------------------- helpers ------------------------------------------
__device__ __forceinline__ unsigned smem_u32(const void* p) {
    return (unsigned)__cvta_generic_to_shared(p);
}
__device__ __forceinline__ void ldsm_x4(uint32_t& r0, uint32_t& r1,
                                        uint32_t& r2, uint32_t& r3, unsigned addr) {
    asm volatile("ldmatrix.sync.aligned.m8n8.x4.shared.b16 {%0,%1,%2,%3}, [%4];"
                 : "=r"(r0), "=r"(r1), "=r"(r2), "=r"(r3) : "r"(addr));
}
__device__ __forceinline__ void ldsm_x2(uint32_t& r0, uint32_t& r1, unsigned addr) {
    asm volatile("ldmatrix.sync.aligned.m8n8.x2.shared.b16 {%0,%1}, [%2];"
                 : "=r"(r0), "=r"(r1) : "r"(addr));
}
__device__ __forceinline__ void mma16816(float& c0, float& c1, float& c2, float& c3,
                                         uint32_t a0, uint32_t a1, uint32_t a2, uint32_t a3,
                                         uint32_t b0, uint32_t b1) {
    asm volatile("mma.sync.aligned.m16n8k16.row.col.f32.bf16.bf16.f32 "
                 "{%0,%1,%2,%3}, {%4,%5,%6,%7}, {%8,%9}, {%0,%1,%2,%3};"
                 : "+f"(c0), "+f"(c1), "+f"(c2), "+f"(c3)
                 : "r"(a0), "r"(a1), "r"(a2), "r"(a3), "r"(b0), "r"(b1));
}

// ------------------------- K0: weight layout prep ---------------------------
__global__ void k0_prep(const float* __restrict__ W2_in,
                        const float* __restrict__ W2_rec)
{
    int j = blockIdx.x;        // presyn 0..255
    int n = threadIdx.x;       // postsyn 0..255
    g_W2recTp[j * NN + n] = W2_rec[n * NN + j];
    g_W2inQ[(((n >> 6) * 256) + j) * 64 + (n & 63)] = W2_in[n * NN + j];
}

// ------------------------- K1: spikify + i1 GEMM via tensor cores -----------
// grid 4000 x 512. CTA: 64 rows (one t) x 256 n, K=120 padded to 128.
// Exact bf16 hi/lo split of W1; xs in {-1,0,1} is bf16-exact. 16 warps,
// warp = (m-tile = warp&3, n-half = warp>>2 -> 64 n). Row stride 136 halves
// (272 B) => ldmatrix conflict-free.
#define K1_LDK 136
#define K1_SMEM (64*K1_LDK*2 + 2*256*K1_LDK*2)   // 156672
__global__ void __launch_bounds__(512, 1)
k1_gemm1(const float* __restrict__ x, const float* __restrict__ thrp,
         const float* __restrict__ W1, const float* __restrict__ b1)
{
    extern __shared__ char smraw[];
    __nv_bfloat16* xs  = (__nv_bfloat16*)smraw;                        // [64][136]
    __nv_bfloat16* whi = (__nv_bfloat16*)(smraw + 64*K1_LDK*2);        // [256][136]
    __nv_bfloat16* wlo = (__nv_bfloat16*)(smraw + 64*K1_LDK*2 + 256*K1_LDK*2);

    const int tid = threadIdx.x;
    const int p0  = blockIdx.x * 64;
    const int t   = p0 >> 9;
    const int b0  = p0 & 511;
    const float thr = *thrp;

    // ---- W1 -> exact bf16 hi/lo split in smem ----
    for (int i4 = tid; i4 < 7680; i4 += 512) {       // 7680 float4 = 256x120
        float4 v = ((const float4*)W1)[i4];
        int n = i4 / 30, k = (i4 % 30) * 4;
        float f[4] = {v.x, v.y, v.z, v.w};
        unsigned short h[4], l[4];
        #pragma unroll
        for (int u = 0; u < 4; u++) {
            __nv_bfloat16 hb = __float2bfloat16(f[u]);
            __nv_bfloat16 lb = __float2bfloat16(f[u] - __bfloat162float(hb));
            h[u] = __bfloat16_as_ushort(hb);
            l[u] = __bfloat16_as_ushort(lb);
        }
        uint2 ph, pl;
        ph.x = (unsigned)h[0] | ((unsigned)h[1] << 16);
        ph.y = (unsigned)h[2] | ((unsigned)h[3] << 16);
        pl.x = (unsigned)l[0] | ((unsigned)l[1] << 16);
        pl.y = (unsigned)l[2] | ((unsigned)l[3] << 16);
        *(uint2*)&whi[n * K1_LDK + k] = ph;
        *(uint2*)&wlo[n * K1_LDK + k] = pl;
    }
    // zero pad k = 120..127
    {
        const __nv_bfloat16 z = __float2bfloat16(0.0f);
        for (int i = tid; i < 256 * 8; i += 512) {
            int n = i >> 3, k = 120 + (i & 7);
            whi[n * K1_LDK + k] = z;
            wlo[n * K1_LDK + k] = z;
        }
        for (int i = tid; i < 64 * 8; i += 512) {
            int r = i >> 3, k = 120 + (i & 7);
            xs[r * K1_LDK + k] = z;
        }
    }
    // ---- spikify -> xs bf16 ----
    for (int i = tid; i < 64 * CD; i += 512) {
        int r  = i / CD;
        int cd = i % CD;
        int c  = cd / DD, d = cd % DD;
        float xv = x[(((size_t)(b0 + r) * CC + c) * TT + t) * DD + d];
        float s  = (xv > thr) ? 1.0f : ((xv < -thr) ? -1.0f : 0.0f);
        xs[r * K1_LDK + cd] = __float2bfloat16(s);
    }
    __syncthreads();

    // ---- tensor-core main loop ----
    const int warp = tid >> 5, lane = tid & 31;
    const int mb = (warp & 3) * 16;       // row base
    const int nb = (warp >> 2) * 64;      // n base

    float acc[8][4];
    #pragma unroll
    for (int j = 0; j < 8; j++)
        #pragma unroll
        for (int u = 0; u < 4; u++) acc[j][u] = 0.0f;

    const unsigned a_base  = smem_u32(xs)  + (unsigned)(mb + (lane & 15)) * (K1_LDK * 2)
                                           + ((lane >> 4) << 4);
    const unsigned bkoff   = ((lane >> 3) & 1) << 4;
    const unsigned bh_base = smem_u32(whi) + (unsigned)(nb + (lane & 7)) * (K1_LDK * 2) + bkoff;
    const unsigned bl_base = smem_u32(wlo) + (unsigned)(nb + (lane & 7)) * (K1_LDK * 2) + bkoff;

    #pragma unroll
    for (int kt = 0; kt < 8; kt++) {
        uint32_t a0, a1, a2, a3;
        ldsm_x4(a0, a1, a2, a3, a_base + kt * 32);
        #pragma unroll
        for (int j = 0; j < 8; j++) {
            uint32_t br0, br1;
            ldsm_x2(br0, br1, bh_base + (unsigned)j * (8 * K1_LDK * 2) + kt * 32);
            mma16816(acc[j][0], acc[j][1], acc[j][2], acc[j][3],
                     a0, a1, a2, a3, br0, br1);
            ldsm_x2(br0, br1, bl_base + (unsigned)j * (8 * K1_LDK * 2) + kt * 32);
            mma16816(acc[j][0], acc[j][1], acc[j][2], acc[j][3],
                     a0, a1, a2, a3, br0, br1);
        }
    }

    // ---- epilogue: bias + store ----
    const int g  = lane >> 2, tg = lane & 3;
    const int r0 = mb + g, r1 = r0 + 8;
    #pragma unroll
    for (int j = 0; j < 8; j++) {
        int n = nb + j * 8 + tg * 2;
        float2 bv = *(const float2*)&b1[n];
        size_t base0 = (size_t)t * BN + (size_t)(b0 + r0) * NN + n;
        size_t base1 = (size_t)t * BN + (size_t)(b0 + r1) * NN + n;
        *(float2*)&g_i1[base0] = make_float2(acc[j][0] + bv.x, acc[j][1] + bv.y);
        *(float2*)&g_i1[base1] = make_float2(acc[j][2] + bv.x, acc[j][3] + bv.y);
    }
}

// ------------------------- K2: layer-1 ALIF scan -> compacted s1 lists ------
__global__ void __launch_bounds__(256)
k2_scan1(const float* __restrict__ tau_adp1, const float* __restrict__ tau_m1)
{
    __shared__ unsigned swords[2][8];

    const int b    = blockIdx.x;
    const int tid  = threadIdx.x;
    const int n    = tid;
    const int lane = tid & 31;
    const int wid  = tid >> 5;
    const unsigned ltm = (1u << lane) - 1u;

    const float alpha = __expf(-1.0f / tau_m1[n]);
    const float rho   = __expf(-1.0f / tau_adp1[n]);
    const float ca = 1.0f - alpha, cr = 1.0f - rho;

    float m = 0.f, a = B_J0, s = 0.f;
    const float* ip = g_i1 + (size_t)b * NN + n;

    for (int t4 = 0; t4 < TT; t4 += 4) {
        float iv[4];
        #pragma unroll
        for (int k = 0; k < 4; k++) iv[k] = ip[(size_t)(t4 + k) * BN];
        #pragma unroll
        for (int k = 0; k < 4; k++) {
            const int t = t4 + k;
            a = rho * a + cr * s;
            float Bth = B_J0 + BETA * a;
            m = alpha * m + ca * iv[k] - Bth * s;
            s = (m - Bth > 0.f) ? 1.f : 0.f;
            unsigned bal = __ballot_sync(0xffffffffu, s > 0.5f);
            if (lane == 0) swords[t & 1][wid] = bal;
            __syncthreads();
            unsigned wv[8];
            #pragma unroll
            for (int w = 0; w < 8; w++) wv[w] = swords[t & 1][w];
            int off = 0, myoff = 0;
            #pragma unroll
            for (int w = 0; w < 8; w++) {
                if (w == wid) myoff = off;
                off += __popc(wv[w]);
            }
            unsigned wd = wv[wid];
            if ((wd >> lane) & 1u)
                g_lst[(size_t)(t * BB + b) * 256 + myoff + __popc(wd & ltm)] =
                    (unsigned char)(wid * 32 + lane);
            if (tid == 0) g_cnt[t * BB + b] = off;
        }
    }
}

// ------------------------- K2.5: i2in = b2 + s1 @ W2_in^T (proven R5) -------
#define K25_SMEM (64*1024 + 8*2*64*4)
__global__ void __launch_bounds__(256, 2)
k25_gemm2in(const float* __restrict__ b2_in, const float* __restrict__ b2_rec)
{
    extern __shared__ float sm[];
    float2*   w2  = (float2*)sm;                  // [j*32+lane] pairs
    unsigned* lsb = (unsigned*)(sm + 16384);      // [8 warps][2][64]

    const int idx  = blockIdx.x;
    const int q    = idx & 3;
    const int bh   = (idx >> 2) & 1;
    const int t    = idx >> 3;
    const int tid  = threadIdx.x;
    const int lane = tid & 31;
    const int wid  = tid >> 5;

    {
        const float4* src = (const float4*)(g_W2inQ + q * 256 * 64);
        float4* dst = (float4*)sm;
        for (int i = tid; i < 4096; i += 256) dst[i] = src[i];
    }
    const int n0 = q * 64 + lane * 2;
    const float2 bias2 = make_float2(b2_in[n0] + b2_rec[n0],
                                     b2_in[n0 + 1] + b2_rec[n0 + 1]);
    __syncthreads();

    const int bbase = bh * 256 + wid * 32;
    const int cb    = t * BB + bbase;
    const int mycnt = g_cnt[cb + lane];
    unsigned* mybuf = lsb + wid * 128;

    {
        int c0  = __shfl_sync(0xffffffffu, mycnt, 0);
        int nch = (c0 + 15) >> 4;
        if (lane < nch) {
            uint4 v = ((const uint4*)(g_lst + (size_t)cb * 256))[lane];
            unsigned* d = mybuf + lane * 4;
            d[0] = v.x; d[1] = v.y; d[2] = v.z; d[3] = v.w;
        }
        __syncwarp();
    }

    for (int i = 0; i < 32; i++) {
        uint4 vn = make_uint4(0, 0, 0, 0);
        int nchn = 0;
        if (i + 1 < 32) {
            int cn = __shfl_sync(0xffffffffu, mycnt, i + 1);
            nchn = (cn + 15) >> 4;
            if (lane < nchn)
                vn = ((const uint4*)(g_lst + (size_t)(cb + i + 1) * 256))[lane];
        }
        const int cnt = __shfl_sync(0xffffffffu, mycnt, i);
        const unsigned* lb = mybuf + (i & 1) * 64;

        float2 acc = bias2;
        int k = 0;
        for (; k + 4 <= cnt; k += 4) {
            unsigned w = lb[k >> 2];
            int j0 = w & 255, j1 = (w >> 8) & 255, j2 = (w >> 16) & 255, j3 = w >> 24;
            float2 v0 = w2[j0 * 32 + lane];
            float2 v1 = w2[j1 * 32 + lane];
            float2 v2 = w2[j2 * 32 + lane];
            float2 v3 = w2[j3 * 32 + lane];
            acc.x += v0.x; acc.y += v0.y;
            acc.x += v1.x; acc.y += v1.y;
            acc.x += v2.x; acc.y += v2.y;
            acc.x += v3.x; acc.y += v3.y;
        }
        if (k < cnt) {
            unsigned w = lb[k >> 2];
            for (; k < cnt; k++) {
                int j = (w >> (8 * (k & 3))) & 255;
                float2 v = w2[j * 32 + lane];
                acc.x += v.x; acc.y += v.y;
            }
        }

        ((float2*)(g_i1 + (size_t)t * BN + (size_t)(bbase + i) * NN + q * 64))[lane] = acc;

        if (i + 1 < 32 && lane < nchn) {
            unsigned* d = mybuf + ((i + 1) & 1) * 64 + lane * 4;
            d[0] = vn.x; d[1] = vn.y; d[2] = vn.z; d[3] = vn.w;
        }
        __syncwarp();
    }
}

// ------------------------- K3: sequential layer-2(rec) + layer-3 (R5) -------
// 512 CTAs x 256 threads (1 neuron/thread). i2in streamed with register
// prefetch; s2 gather list-compacted, 8-way batched LDG.32, in-order adds.
__global__ void __launch_bounds__(256)
k3_recurrent(const float* __restrict__ W3, const float* __restrict__ b3,
             const float* __restrict__ tau_adp2, const float* __restrict__ tau_m2,
             const float* __restrict__ tau_m3)
{
    __shared__ float    W3s[OUTN * 257];
    __shared__ unsigned words[8];
    __shared__ int      lst2[256];

    const int b    = blockIdx.x;
    const int tid  = threadIdx.x;
    const int n    = tid;
    const int lane = tid & 31;
    const int wid  = tid >> 5;
    const unsigned ltm = (1u << lane) - 1u;

    for (int i = tid; i < OUTN * NN; i += 256)
        W3s[(i >> 8) * 257 + (i & 255)] = W3[i];
    if (tid < 8) words[tid] = 0u;

    const float al = __expf(-1.0f / tau_m2[n]);
    const float rh = __expf(-1.0f / tau_adp2[n]);
    float m2 = 0.f, a2 = B_J0, s2 = 0.f;

    float al3 = 1.f, m3 = 0.f, accr = 0.f, b3v = 0.f;
    if (tid < OUTN) { al3 = __expf(-1.0f / tau_m3[tid]); b3v = b3[tid]; }

    const float* __restrict__ w2rf = g_W2recTp;
    const float* __restrict__ i2p  = g_i1 + (size_t)b * NN + n;

    __syncthreads();

    float iv = i2p[0];

    for (int t = 0; t < TT; t++) {
        __syncthreads();   // prev ballots visible; lst2 free

        const int tn = (t + 1 < TT) ? (t + 1) : t;
        float nv = i2p[(size_t)tn * BN];

        // deferred layer-3 for step t-1 (warp-0 lanes 0..11)
        if (tid < OUTN && t > 0) {
            float i3 = b3v;
            const float* wr = &W3s[tid * 257];
            #pragma unroll
            for (int w = 0; w < 8; w++) {
                unsigned mm = words[w];
                int base = w * 32;
                while (mm) {
                    int j = __ffs((int)mm) - 1;
                    mm &= mm - 1;
                    i3 += wr[base + j];
                }
            }
            m3 = al3 * m3 + (1.0f - al3) * i3;
            accr += m3;
        }

        // compaction (ascending j)
        unsigned wv[8];
        #pragma unroll
        for (int w = 0; w < 8; w++) wv[w] = words[w];
        int off = 0, myoff = 0;
        #pragma unroll
        for (int w = 0; w < 8; w++) {
            if (w == wid) myoff = off;
            off += __popc(wv[w]);
        }
        const int cnt2 = off;
        unsigned wd = wv[wid];
        if ((wd >> lane) & 1u)
            lst2[myoff + __popc(wd & ltm)] = wid * 32 + lane;
        __syncthreads();   // lists ready

        // gather: 8-way batched independent LDG.32, in-order adds
        float i2 = iv;
        {
            int k = 0;
            for (; k + 8 <= cnt2; k += 8) {
                int j0 = lst2[k],     j1 = lst2[k + 1], j2 = lst2[k + 2], j3 = lst2[k + 3];
                int j4 = lst2[k + 4], j5 = lst2[k + 5], j6 = lst2[k + 6], j7 = lst2[k + 7];
                float v0 = w2rf[j0 * NN + n];
                float v1 = w2rf[j1 * NN + n];
                float v2 = w2rf[j2 * NN + n];
                float v3 = w2rf[j3 * NN + n];
                float v4 = w2rf[j4 * NN + n];
                float v5 = w2rf[j5 * NN + n];
                float v6 = w2rf[j6 * NN + n];
                float v7 = w2rf[j7 * NN + n];
                i2 += v0; i2 += v1; i2 += v2; i2 += v3;
                i2 += v4; i2 += v5; i2 += v6; i2 += v7;
            }
            for (; k < cnt2; k++) i2 += w2rf[lst2[k] * NN + n];
        }

        // ALIF update
        a2 = rh * a2 + (1.0f - rh) * s2;
        float Bth = B_J0 + BETA * a2;
        m2 = al * m2 + (1.0f - al) * i2 - Bth * s2;
        s2 = (m2 - Bth > 0.f) ? 1.f : 0.f;

        unsigned bal = __ballot_sync(0xffffffffu, s2 > 0.5f);
        if (lane == 0) words[wid] = bal;
        iv = nv;
    }

    // final deferred layer-3 (step TT-1)
    __syncthreads();
    if (tid < OUTN) {
        float i3 = b3v;
        const float* wr = &W3s[tid * 257];
        #pragma unroll
        for (int w = 0; w < 8; w++) {
            unsigned mm = words[w];
            int base = w * 32;
            while (mm) {
                int j = __ffs((int)mm) - 1;
                mm &= mm - 1;
                i3 += wr[base + j];
            }
        }
        m3 = al3 * m3 + (1.0f - al3) * i3;
        accr += m3;
        g_acc[b * OUTN + tid] = accr;
    }
}

// ------------------------- K4: log-softmax ----------------------------------
__global__ void __launch_bounds__(256)
k4_softmax(float* __restrict__ out)
{
    int b = blockIdx.x * 256 + threadIdx.x;
    if (b >= BB) return;
    float v[OUTN];
    float mx = -1e30f;
    #pragma unroll
    for (int o = 0; o < OUTN; o++) {
        v[o] = g_acc[b * OUTN + o] * (1.0f / (float)TT);
        mx = fmaxf(mx, v[o]);
    }
    float sum = 0.f;
    #pragma unroll
    for (int o = 0; o < OUTN; o++) sum += __expf(v[o] - mx);
    float lse = mx + __logf(sum);
    #pragma unroll
    for (int o = 0; o < OUTN; o++) out[b * OUTN + o] = v[o] - lse;
}

// ------------------------- launch -------------------------------------------
extern "C" void kernel_launch(void* const* d_in, const int* in_sizes, int n_in,
                              void* d_out, int out_size)
{
    const float* x        = (const float*)d_in[0];
    const float* thr      = (const float*)d_in[1];
    const float* W1       = (const float*)d_in[2];
    const float* b1       = (const float*)d_in[3];
    const float* W2_in    = (const float*)d_in[4];
    const float* b2_in    = (const float*)d_in[5];
    const float* W2_rec   = (const float*)d_in[6];
    const float* b2_rec   = (const float*)d_in[7];
    const float* W3       = (const float*)d_in[8];
    const float* b3       = (const float*)d_in[9];
    const float* tau_adp1 = (const float*)d_in[10];
    const float* tau_m1   = (const float*)d_in[11];
    const float* tau_adp2 = (const float*)d_in[12];
    const float* tau_m2   = (const float*)d_in[13];
    const float* tau_m3   = (const float*)d_in[14];
    float* out = (float*)d_out;

    cudaFuncSetAttribute(k1_gemm1,    cudaFuncAttributeMaxDynamicSharedMemorySize, K1_SMEM);
    cudaFuncSetAttribute(k25_gemm2in, cudaFuncAttributeMaxDynamicSharedMemorySize, K25_SMEM);

    k0_prep<<<NN, NN>>>(W2_in, W2_rec);
    k1_gemm1<<<(TT * BB) / 64, 512, K1_SMEM>>>(x, thr, W1, b1);
    k2_scan1<<<BB, 256>>>(tau_adp1, tau_m1);
    k25_gemm2in<<<8 * TT, 256, K25_SMEM>>>(b2_in, b2_rec);
    k3_recurrent<<<BB, 256>>>(W3, b3, tau_adp2, tau_m2, tau_m3);
    k4_softmax<<<(BB + 255) / 256, 256>>>(out);
}